// round 11
// baseline (speedup 1.0000x reference)
#include <cuda_runtime.h>
#include <cuda_fp16.h>
#include <math.h>

#define NN 100000
#define NE 1600000
#define EP (NE + NN)          // edges + self loops
#define HID 64
#define LAYERS 3

#define SCAN_T 512
#define NB1 ((NN + SCAN_T - 1) / SCAN_T)   // 196

// ---------------- scratch (device globals; no allocation allowed) ----------
__device__ float   g_x[NN * HID];    // current features / residual (fp32)
__device__ __half2 g_xlh[NN * 32];   // xl fp16: 64 halves = 128B per node row
__device__ __half2 g_xrh[NN * 32];   // xr fp16: same packing
__device__ int     g_deg[NN];        // histogram, then scatter cursor
__device__ int     g_off[NN + 1];    // CSR offsets (exclusive scan)
__device__ int     g_srcs[EP];       // CSR: src node per incoming edge
__device__ int     g_bsum[NB1];      // scan block sums

__device__ __forceinline__ unsigned smem_u32(const void* p) {
    return (unsigned)__cvta_generic_to_shared(p);
}

// ---------------- 1) input projection + zero the degree histogram ----------
__global__ void k_proj(const float* __restrict__ coords,
                       const float* __restrict__ Wp,
                       const float* __restrict__ bp) {
    int i = blockIdx.x * blockDim.x + threadIdx.x;
    if (i >= NN * HID) return;
    int n = i >> 6, c = i & 63;
    float c0 = coords[n * 2 + 0];
    float c1 = coords[n * 2 + 1];
    g_x[i] = fmaf(c0, Wp[c], fmaf(c1, Wp[64 + c], bp[c]));
    if (i < NN) g_deg[i] = 0;
}

// ---------------- 2) CSR build: histogram over destinations ----------------
__global__ void k_hist(const int* __restrict__ ei) {
    int e = blockIdx.x * blockDim.x + threadIdx.x;
    if (e >= EP) return;
    int d = (e < NE) ? ei[NE + e] : (e - NE);
    atomicAdd(&g_deg[d], 1);
}

// ---------------- 3) scan level 1 (warp-shuffle based) ---------------------
__global__ void k_scan1() {
    __shared__ int wsum[SCAN_T / 32];
    int t = threadIdx.x, b = blockIdx.x, i = b * SCAN_T + t;
    int lane = t & 31, wid = t >> 5;
    int v = (i < NN) ? g_deg[i] : 0;
    int x = v;
#pragma unroll
    for (int o = 1; o < 32; o <<= 1) {
        int u = __shfl_up_sync(0xffffffffu, x, o);
        if (lane >= o) x += u;
    }
    if (lane == 31) wsum[wid] = x;
    __syncthreads();
    if (wid == 0) {
        int ws = (lane < SCAN_T / 32) ? wsum[lane] : 0;
        int y = ws;
#pragma unroll
        for (int o = 1; o < 16; o <<= 1) {
            int u = __shfl_up_sync(0xffffffffu, y, o);
            if (lane >= o) y += u;
        }
        if (lane < SCAN_T / 32) wsum[lane] = y - ws;
        if (lane == SCAN_T / 32 - 1) g_bsum[b] = y;
    }
    __syncthreads();
    if (i < NN) g_off[i] = x - v + wsum[wid];
}

// ---------------- 4) scan level 2 fused: add prefix of block sums ----------
__global__ void k_scan3() {
    __shared__ int sprev;
    int t = threadIdx.x, b = blockIdx.x, i = b * SCAN_T + t;
    if (t < 32) {
        int acc = 0;
        for (int j = t; j < b; j += 32) acc += g_bsum[j];
#pragma unroll
        for (int o = 16; o; o >>= 1) acc += __shfl_xor_sync(0xffffffffu, acc, o);
        if (t == 0) sprev = acc;
    }
    __syncthreads();
    int prev = sprev;
    if (i < NN) {
        int o = g_off[i] + prev;
        g_off[i] = o;
        g_deg[i] = o;
    }
    if (i == 0) g_off[NN] = EP;
}

// ---------------- 5) CSR scatter --------------------------------------------
__global__ void k_scatter(const int* __restrict__ ei) {
    int e = blockIdx.x * blockDim.x + threadIdx.x;
    if (e >= EP) return;
    int s, d;
    if (e < NE) { s = ei[e]; d = ei[NE + e]; }
    else        { s = e - NE; d = s; }
    int pos = atomicAdd(&g_deg[d], 1);
    g_srcs[pos] = s;
}

// ---------------- 6) tensor-core GEMM: [xl|xr] = x @ [Wl|Wr] + bias ---------
// mma.m16n8k16 f16 inputs, f32 accumulate. Both outputs stored fp16 (128B/row).
__global__ __launch_bounds__(256)
void k_gemm(const float* __restrict__ Wl, const float* __restrict__ bl,
            const float* __restrict__ Wr, const float* __restrict__ br) {
    __shared__ __align__(16) __half xsh[128][72];   // stride 144B
    __shared__ __align__(16) __half wsh[64][136];   // stride 272B
    int tid  = threadIdx.x;
    int row0 = blockIdx.x * 128;

    for (int j = tid; j < 64 * 128 / 4; j += 256) {
        int k = j >> 5;
        int c = (j << 2) & 127;
        float4 v = (c < 64) ? *(const float4*)&Wl[k * 64 + c]
                            : *(const float4*)&Wr[k * 64 + (c - 64)];
        __half2* dst = (__half2*)&wsh[k][c];
        dst[0] = __floats2half2_rn(v.x, v.y);
        dst[1] = __floats2half2_rn(v.z, v.w);
    }
    for (int j = tid; j < 128 * 64 / 4; j += 256) {
        int r = j >> 4;
        int c = (j << 2) & 63;
        int row = row0 + r;
        float4 v = (row < NN) ? *(const float4*)&g_x[row * 64 + c]
                              : make_float4(0.f, 0.f, 0.f, 0.f);
        __half2* dst = (__half2*)&xsh[r][c];
        dst[0] = __floats2half2_rn(v.x, v.y);
        dst[1] = __floats2half2_rn(v.z, v.w);
    }
    __syncthreads();

    int wid  = tid >> 5;
    int lane = tid & 31;
    int g    = lane >> 2;
    int tig  = lane & 3;

    unsigned A[4][4];
    {
        int m = lane >> 3, r = lane & 7;
#pragma unroll
        for (int ks = 0; ks < 4; ks++) {
            unsigned addr = smem_u32(&xsh[wid * 16 + (m & 1) * 8 + r]
                                        [ks * 16 + (m >> 1) * 8]);
            asm volatile("ldmatrix.sync.aligned.m8n8.x4.shared.b16 "
                         "{%0,%1,%2,%3}, [%4];"
                         : "=r"(A[ks][0]), "=r"(A[ks][1]),
                           "=r"(A[ks][2]), "=r"(A[ks][3]) : "r"(addr));
        }
    }

#pragma unroll
    for (int nt = 0; nt < 16; nt++) {
        float c0 = 0.f, c1 = 0.f, c2 = 0.f, c3 = 0.f;
#pragma unroll
        for (int ks = 0; ks < 4; ks++) {
            unsigned B0, B1;
            int m = (lane >> 3) & 1, r = lane & 7;
            unsigned addr = smem_u32(&wsh[ks * 16 + m * 8 + r][nt * 8]);
            asm volatile("ldmatrix.sync.aligned.m8n8.x2.trans.shared.b16 "
                         "{%0,%1}, [%2];"
                         : "=r"(B0), "=r"(B1) : "r"(addr));
            asm volatile("mma.sync.aligned.m16n8k16.row.col.f32.f16.f16.f32 "
                         "{%0,%1,%2,%3}, {%4,%5,%6,%7}, {%8,%9}, {%0,%1,%2,%3};"
                         : "+f"(c0), "+f"(c1), "+f"(c2), "+f"(c3)
                         : "r"(A[ks][0]), "r"(A[ks][1]),
                           "r"(A[ks][2]), "r"(A[ks][3]), "r"(B0), "r"(B1));
        }
        int col   = nt * 8 + tig * 2;
        int row_a = row0 + wid * 16 + g;
        int row_b = row_a + 8;
        if (col < 64) {                          // xl -> fp16
            float bx = bl[col], by = bl[col + 1];
            if (row_a < NN)
                g_xlh[row_a * 32 + (col >> 1)] = __floats2half2_rn(c0 + bx, c1 + by);
            if (row_b < NN)
                g_xlh[row_b * 32 + (col >> 1)] = __floats2half2_rn(c2 + bx, c3 + by);
        } else {                                 // xr -> fp16
            int cc = col - 64;
            float bx = br[cc], by = br[cc + 1];
            if (row_a < NN)
                g_xrh[row_a * 32 + (cc >> 1)] = __floats2half2_rn(c0 + bx, c1 + by);
            if (row_b < NN)
                g_xrh[row_b * 32 + (cc >> 1)] = __floats2half2_rn(c2 + bx, c3 + by);
        }
    }
}

// ---------------- 7) FUSED: per-dst attention + softmax + ELU + LN ---------
// One warp per node; 4 groups of 8 lanes; each group = one edge; each lane
// owns 8 dims (16B fp16). One LDG.128 warp-instr covers 4 edges.
__device__ __forceinline__ float nan2num(float o) {
    if (!isfinite(o)) o = isnan(o) ? 0.f : (o > 0.f ? 1e6f : -1e6f);
    return o;
}

__device__ __forceinline__ void cvt8(uint4 u, float* f) {
    float2 t;
    t = __half22float2(*(__half2*)&u.x); f[0] = t.x; f[1] = t.y;
    t = __half22float2(*(((__half2*)&u.x) + 1)); f[2] = t.x; f[3] = t.y;
    t = __half22float2(*(__half2*)&u.z); f[4] = t.x; f[5] = t.y;
    t = __half22float2(*(((__half2*)&u.z) + 1)); f[6] = t.x; f[7] = t.y;
}

__global__ __launch_bounds__(256)
void k_aggr_ln(const float* __restrict__ att,
               const float* __restrict__ bias_out,
               const float* __restrict__ gamma, const float* __restrict__ beta,
               float* __restrict__ dout, int to_dout) {
    int w = (blockIdx.x * blockDim.x + threadIdx.x) >> 5;   // node id
    if (w >= NN) return;
    int lane = threadIdx.x & 31;
    int grp  = lane >> 3;            // edge group 0..3
    int jl   = lane & 7;             // dim-chunk 0..7 (dims jl*8..jl*8+7)

    int beg = g_off[w], end = g_off[w + 1];
    int s_fb = __ldg(&g_srcs[beg]);

    const uint4* xlh4 = (const uint4*)g_xlh;
    const uint4* xrh4 = (const uint4*)g_xrh;

    float xr[8];
    cvt8(__ldg(&xrh4[w * 8 + jl]), xr);
    float at[8];
    *(float4*)&at[0] = *(const float4*)&att[jl * 8];
    *(float4*)&at[4] = *(const float4*)&att[jl * 8 + 4];

    float acc[8] = {0.f, 0.f, 0.f, 0.f, 0.f, 0.f, 0.f, 0.f};
    float dsum = 0.f;

    int trips = (end - beg + 3) >> 2;            // deg >= 1 (self loop)
    for (int k = 0; k < trips; k++) {
        int i = beg + (k << 2) + grp;
        bool v = (i < end);
        int  s = v ? __ldg(&g_srcs[i]) : s_fb;
        float a[8];
        cvt8(__ldg(&xlh4[s * 8 + jl]), a);

        float p = 0.f;
#pragma unroll
        for (int j = 0; j < 8; j++) {
            float t = a[j] + xr[j];
            p = fmaf(fmaxf(t, 0.2f * t), at[j], p);   // LeakyReLU via fmax
        }
        // reduce over 4 lanes of the same head (lanes jl 0-3 = head0, 4-7 = head1)
        p += __shfl_xor_sync(0xffffffffu, p, 1, 4);
        p += __shfl_xor_sync(0xffffffffu, p, 2, 4);
        float ex = v ? __expf(p) : 0.f;          // scores O(1): no max shift
#pragma unroll
        for (int j = 0; j < 8; j++) acc[j] = fmaf(ex, a[j], acc[j]);
        dsum += ex;
    }

    // combine the 4 edge-groups (xor 8/16 symmetric butterflies)
#pragma unroll
    for (int j = 0; j < 8; j++) {
        acc[j] += __shfl_xor_sync(0xffffffffu, acc[j], 8);
        acc[j] += __shfl_xor_sync(0xffffffffu, acc[j], 16);
    }
    dsum += __shfl_xor_sync(0xffffffffu, dsum, 8);
    dsum += __shfl_xor_sync(0xffffffffu, dsum, 16);

    // normalize + bias_out + ELU + residual (8 dims per lane, all lanes replicate)
    float inv = 1.f / (dsum + 1e-16f);           // lane's own head denom
    float y[8];
    {
        float bo[8], rx[8];
        *(float4*)&bo[0] = *(const float4*)&bias_out[jl * 8];
        *(float4*)&bo[4] = *(const float4*)&bias_out[jl * 8 + 4];
        *(float4*)&rx[0] = *(const float4*)&g_x[w * 64 + jl * 8];
        *(float4*)&rx[4] = *(const float4*)&g_x[w * 64 + jl * 8 + 4];
#pragma unroll
        for (int j = 0; j < 8; j++) {
            float t = acc[j] * inv + bo[j];
            t = t > 0.f ? t : expm1f(t);         // ELU
            y[j] = t + rx[j];                    // residual
        }
    }

    // LayerNorm over 64 dims: local sum of 8 + butterfly over 8 lanes
    float sum = 0.f;
#pragma unroll
    for (int j = 0; j < 8; j++) sum += y[j];
#pragma unroll
    for (int o = 1; o < 8; o <<= 1)
        sum += __shfl_xor_sync(0xffffffffu, sum, o, 8);
    float mu = sum * (1.f / 64.f);
    float vs = 0.f;
#pragma unroll
    for (int j = 0; j < 8; j++) {
        y[j] -= mu;
        vs = fmaf(y[j], y[j], vs);
    }
#pragma unroll
    for (int o = 1; o < 8; o <<= 1)
        vs += __shfl_xor_sync(0xffffffffu, vs, o, 8);
    float r = rsqrtf(vs * (1.f / 64.f) + 1e-5f);

    if (grp == 0) {
        float gm[8], bt[8], o8[8];
        *(float4*)&gm[0] = *(const float4*)&gamma[jl * 8];
        *(float4*)&gm[4] = *(const float4*)&gamma[jl * 8 + 4];
        *(float4*)&bt[0] = *(const float4*)&beta[jl * 8];
        *(float4*)&bt[4] = *(const float4*)&beta[jl * 8 + 4];
#pragma unroll
        for (int j = 0; j < 8; j++)
            o8[j] = nan2num(fmaf(y[j] * r, gm[j], bt[j]));
        float* outp = to_dout ? dout : g_x;
        *(float4*)&outp[w * 64 + jl * 8]     = *(float4*)&o8[0];
        *(float4*)&outp[w * 64 + jl * 8 + 4] = *(float4*)&o8[4];
    }
}

// ---------------- host driver ----------------------------------------------
extern "C" void kernel_launch(void* const* d_in, const int* in_sizes, int n_in,
                              void* d_out, int out_size) {
    const float* coords   = (const float*)d_in[0];
    const int*   ei       = (const int*)  d_in[1];   // int32 (JAX x64 disabled)
    const float* Wp       = (const float*)d_in[2];
    const float* bp       = (const float*)d_in[3];
    const float* Wl       = (const float*)d_in[4];
    const float* bl       = (const float*)d_in[5];
    const float* Wr       = (const float*)d_in[6];
    const float* br       = (const float*)d_in[7];
    const float* att      = (const float*)d_in[8];
    const float* bias_out = (const float*)d_in[9];
    const float* gamma    = (const float*)d_in[10];
    const float* beta     = (const float*)d_in[11];
    float*       outp     = (float*)d_out;

    const int TB = 256;
    const int grid_nh = (NN * HID + TB - 1) / TB;    // 25000
    const int grid_gm = (NN + 127) / 128;            // 782
    const int grid_ep = (EP + TB - 1) / TB;          // 6641
    const int grid_ag = (NN * 32 + TB - 1) / TB;     // 12500 (warp/node)

    // projection + CSR build — once, reused by all layers.
    // aggr layer 0 lands at profiled position later; gemm0 is 4th launch.
    k_proj<<<grid_nh, TB>>>(coords, Wp, bp);
    k_hist<<<grid_ep, TB>>>(ei);
    k_scan1<<<NB1, SCAN_T>>>();
    k_gemm<<<grid_gm, TB>>>(Wl, bl, Wr, br);         // layer 0 (needs proj only)
    k_scan3<<<NB1, SCAN_T>>>();
    k_scatter<<<grid_ep, TB>>>(ei);

    for (int i = 0; i < LAYERS; i++) {
        if (i > 0)
            k_gemm<<<grid_gm, TB>>>(Wl + i * HID * HID, bl + i * HID,
                                    Wr + i * HID * HID, br + i * HID);
        k_aggr_ln<<<grid_ag, TB>>>(att + i * HID, bias_out + i * HID,
                                   gamma + i * HID, beta + i * HID,
                                   outp, (i == LAYERS - 1) ? 1 : 0);
    }
}

// round 12
// speedup vs baseline: 1.1146x; 1.1146x over previous
#include <cuda_runtime.h>
#include <cuda_fp16.h>
#include <math.h>

#define NN 100000
#define NE 1600000
#define EP (NE + NN)          // edges + self loops
#define HID 64
#define LAYERS 3

#define SCAN_T 512
#define NB1 ((NN + SCAN_T - 1) / SCAN_T)   // 196

// ---------------- scratch (device globals; no allocation allowed) ----------
__device__ float   g_x[NN * HID];    // current features / residual (fp32)
__device__ __half2 g_xlh[NN * 32];   // xl fp16: 64 halves = 128B per node row
__device__ float   g_xr[NN * HID];   // xr fp32
__device__ int     g_deg[NN];        // histogram, then scatter cursor
__device__ int     g_off[NN + 1];    // CSR offsets (exclusive scan)
__device__ int     g_srcs[EP];       // CSR: src node per incoming edge
__device__ int     g_bsum[NB1];      // scan block sums

__device__ __forceinline__ unsigned smem_u32(const void* p) {
    return (unsigned)__cvta_generic_to_shared(p);
}

// ---------------- 1) input projection + zero the degree histogram ----------
__global__ void k_proj(const float* __restrict__ coords,
                       const float* __restrict__ Wp,
                       const float* __restrict__ bp) {
    int i = blockIdx.x * blockDim.x + threadIdx.x;
    if (i >= NN * HID) return;
    int n = i >> 6, c = i & 63;
    float c0 = coords[n * 2 + 0];
    float c1 = coords[n * 2 + 1];
    g_x[i] = fmaf(c0, Wp[c], fmaf(c1, Wp[64 + c], bp[c]));
    if (i < NN) g_deg[i] = 0;
}

// ---------------- 2) CSR build: histogram over destinations ----------------
__global__ void k_hist(const int* __restrict__ ei) {
    int e = blockIdx.x * blockDim.x + threadIdx.x;
    if (e >= EP) return;
    int d = (e < NE) ? ei[NE + e] : (e - NE);
    atomicAdd(&g_deg[d], 1);
}

// ---------------- 3) scan level 1 (warp-shuffle based) ---------------------
__global__ void k_scan1() {
    __shared__ int wsum[SCAN_T / 32];
    int t = threadIdx.x, b = blockIdx.x, i = b * SCAN_T + t;
    int lane = t & 31, wid = t >> 5;
    int v = (i < NN) ? g_deg[i] : 0;
    int x = v;
#pragma unroll
    for (int o = 1; o < 32; o <<= 1) {
        int u = __shfl_up_sync(0xffffffffu, x, o);
        if (lane >= o) x += u;
    }
    if (lane == 31) wsum[wid] = x;
    __syncthreads();
    if (wid == 0) {
        int ws = (lane < SCAN_T / 32) ? wsum[lane] : 0;
        int y = ws;
#pragma unroll
        for (int o = 1; o < 16; o <<= 1) {
            int u = __shfl_up_sync(0xffffffffu, y, o);
            if (lane >= o) y += u;
        }
        if (lane < SCAN_T / 32) wsum[lane] = y - ws;
        if (lane == SCAN_T / 32 - 1) g_bsum[b] = y;
    }
    __syncthreads();
    if (i < NN) g_off[i] = x - v + wsum[wid];
}

// ---------------- 4) scan level 2 fused: add prefix of block sums ----------
__global__ void k_scan3() {
    __shared__ int sprev;
    int t = threadIdx.x, b = blockIdx.x, i = b * SCAN_T + t;
    if (t < 32) {
        int acc = 0;
        for (int j = t; j < b; j += 32) acc += g_bsum[j];
#pragma unroll
        for (int o = 16; o; o >>= 1) acc += __shfl_xor_sync(0xffffffffu, acc, o);
        if (t == 0) sprev = acc;
    }
    __syncthreads();
    int prev = sprev;
    if (i < NN) {
        int o = g_off[i] + prev;
        g_off[i] = o;
        g_deg[i] = o;
    }
    if (i == 0) g_off[NN] = EP;
}

// ---------------- 5) CSR scatter --------------------------------------------
__global__ void k_scatter(const int* __restrict__ ei) {
    int e = blockIdx.x * blockDim.x + threadIdx.x;
    if (e >= EP) return;
    int s, d;
    if (e < NE) { s = ei[e]; d = ei[NE + e]; }
    else        { s = e - NE; d = s; }
    int pos = atomicAdd(&g_deg[d], 1);
    g_srcs[pos] = s;
}

// ---------------- 6) tensor-core GEMM: [xl|xr] = x @ [Wl|Wr] + bias ---------
// mma.m16n8k16 f16 inputs, f32 accumulate. B-fragments double-buffered so the
// ldmatrix.trans latency of tile nt+1 hides under the 4 mmas of tile nt.
__global__ __launch_bounds__(256)
void k_gemm(const float* __restrict__ Wl, const float* __restrict__ bl,
            const float* __restrict__ Wr, const float* __restrict__ br) {
    __shared__ __align__(16) __half xsh[128][72];   // stride 144B
    __shared__ __align__(16) __half wsh[64][136];   // stride 272B
    int tid  = threadIdx.x;
    int row0 = blockIdx.x * 128;

    for (int j = tid; j < 64 * 128 / 4; j += 256) {
        int k = j >> 5;
        int c = (j << 2) & 127;
        float4 v = (c < 64) ? *(const float4*)&Wl[k * 64 + c]
                            : *(const float4*)&Wr[k * 64 + (c - 64)];
        __half2* dst = (__half2*)&wsh[k][c];
        dst[0] = __floats2half2_rn(v.x, v.y);
        dst[1] = __floats2half2_rn(v.z, v.w);
    }
    for (int j = tid; j < 128 * 64 / 4; j += 256) {
        int r = j >> 4;
        int c = (j << 2) & 63;
        int row = row0 + r;
        float4 v = (row < NN) ? *(const float4*)&g_x[row * 64 + c]
                              : make_float4(0.f, 0.f, 0.f, 0.f);
        __half2* dst = (__half2*)&xsh[r][c];
        dst[0] = __floats2half2_rn(v.x, v.y);
        dst[1] = __floats2half2_rn(v.z, v.w);
    }
    __syncthreads();

    int wid  = tid >> 5;
    int lane = tid & 31;
    int g    = lane >> 2;
    int tig  = lane & 3;
    int bm   = (lane >> 3) & 1, brow = lane & 7;

    unsigned A[4][4];
    {
        int m = lane >> 3, r = lane & 7;
#pragma unroll
        for (int ks = 0; ks < 4; ks++) {
            unsigned addr = smem_u32(&xsh[wid * 16 + (m & 1) * 8 + r]
                                        [ks * 16 + (m >> 1) * 8]);
            asm volatile("ldmatrix.sync.aligned.m8n8.x4.shared.b16 "
                         "{%0,%1,%2,%3}, [%4];"
                         : "=r"(A[ks][0]), "=r"(A[ks][1]),
                           "=r"(A[ks][2]), "=r"(A[ks][3]) : "r"(addr));
        }
    }

    // B double buffer: Bc = current tile, Bn = next tile
    unsigned Bc[4][2], Bn[4][2];
#pragma unroll
    for (int ks = 0; ks < 4; ks++) {
        unsigned addr = smem_u32(&wsh[ks * 16 + bm * 8 + brow][0]);
        asm volatile("ldmatrix.sync.aligned.m8n8.x2.trans.shared.b16 "
                     "{%0,%1}, [%2];"
                     : "=r"(Bc[ks][0]), "=r"(Bc[ks][1]) : "r"(addr));
    }

#pragma unroll
    for (int nt = 0; nt < 16; nt++) {
        if (nt < 15) {
#pragma unroll
            for (int ks = 0; ks < 4; ks++) {
                unsigned addr = smem_u32(&wsh[ks * 16 + bm * 8 + brow]
                                            [(nt + 1) * 8]);
                asm volatile("ldmatrix.sync.aligned.m8n8.x2.trans.shared.b16 "
                             "{%0,%1}, [%2];"
                             : "=r"(Bn[ks][0]), "=r"(Bn[ks][1]) : "r"(addr));
            }
        }
        float c0 = 0.f, c1 = 0.f, c2 = 0.f, c3 = 0.f;
#pragma unroll
        for (int ks = 0; ks < 4; ks++) {
            asm volatile("mma.sync.aligned.m16n8k16.row.col.f32.f16.f16.f32 "
                         "{%0,%1,%2,%3}, {%4,%5,%6,%7}, {%8,%9}, {%0,%1,%2,%3};"
                         : "+f"(c0), "+f"(c1), "+f"(c2), "+f"(c3)
                         : "r"(A[ks][0]), "r"(A[ks][1]),
                           "r"(A[ks][2]), "r"(A[ks][3]),
                           "r"(Bc[ks][0]), "r"(Bc[ks][1]));
        }
        int col   = nt * 8 + tig * 2;
        int row_a = row0 + wid * 16 + g;
        int row_b = row_a + 8;
        if (col < 64) {                          // xl -> fp16
            float bx = bl[col], by = bl[col + 1];
            if (row_a < NN)
                g_xlh[row_a * 32 + (col >> 1)] = __floats2half2_rn(c0 + bx, c1 + by);
            if (row_b < NN)
                g_xlh[row_b * 32 + (col >> 1)] = __floats2half2_rn(c2 + bx, c3 + by);
        } else {                                 // xr -> fp32
            int cc = col - 64;
            float bx = br[cc], by = br[cc + 1];
            if (row_a < NN)
                *(float2*)&g_xr[row_a * 64 + cc] = make_float2(c0 + bx, c1 + by);
            if (row_b < NN)
                *(float2*)&g_xr[row_b * 64 + cc] = make_float2(c2 + bx, c3 + by);
        }
#pragma unroll
        for (int ks = 0; ks < 4; ks++) {
            Bc[ks][0] = Bn[ks][0];
            Bc[ks][1] = Bn[ks][1];
        }
    }
}

// ---------------- 7) FUSED: per-dst attention + softmax + ELU + LN ---------
// One warp per node; 2 halves x unroll 2, software-pipelined prefetch of the
// next iteration's srcs + xl lines (no padding waste: OOB clamps to self-loop).
__device__ __forceinline__ float nan2num(float o) {
    if (!isfinite(o)) o = isnan(o) ? 0.f : (o > 0.f ? 1e6f : -1e6f);
    return o;
}

__device__ __forceinline__ float lrelu(float v) {
    return v > 0.f ? v : 0.2f * v;
}

__device__ __forceinline__ float4 ld_xlh(int s, int l) {
    uint2 u = __ldg((const uint2*)&g_xlh[s * 32 + l * 2]);
    __half2 h0 = *(__half2*)&u.x;
    __half2 h1 = *(__half2*)&u.y;
    float2 f0 = __half22float2(h0);
    float2 f1 = __half22float2(h1);
    return make_float4(f0.x, f0.y, f1.x, f1.y);
}

__global__ __launch_bounds__(256)
void k_aggr_ln(const float* __restrict__ att,
               const float* __restrict__ bias_out,
               const float* __restrict__ gamma, const float* __restrict__ beta,
               float* __restrict__ dout, int to_dout) {
    int w = (blockIdx.x * blockDim.x + threadIdx.x) >> 5;   // node id
    if (w >= NN) return;
    int lane = threadIdx.x & 31;
    int half = lane >> 4;
    int l    = lane & 15;

    int beg = g_off[w], end = g_off[w + 1];
    int s_fb = __ldg(&g_srcs[beg]);

    float4 xr  = *(const float4*)&g_xr[w * 64 + l * 4];
    float4 at4 = *(const float4*)&att[l * 4];

    float4 acc = make_float4(0.f, 0.f, 0.f, 0.f);
    float  dsum = 0.f;

    int iters = (end - beg + 1) >> 1;            // deg >= 1 (self loop)

    // prologue: load iteration-0 pair
    int i0 = beg + half;
    int i1 = i0 + 2;
    bool v0 = (i0 < end);
    bool v1 = (i1 < end);
    int  s0 = v0 ? __ldg(&g_srcs[i0]) : s_fb;
    int  s1 = v1 ? __ldg(&g_srcs[i1]) : s_fb;
    float4 a0 = ld_xlh(s0, l);
    float4 a1 = ld_xlh(s1, l);

    for (int k = 0; k < iters; k += 2) {
        // prefetch iteration k+2 before touching current data
        int i0n = beg + 2 * (k + 2) + half;
        int i1n = i0n + 2;
        bool v0n = (i0n < end);
        bool v1n = (i1n < end);
        int  s0n = v0n ? __ldg(&g_srcs[i0n]) : s_fb;
        int  s1n = v1n ? __ldg(&g_srcs[i1n]) : s_fb;
        float4 a0n = ld_xlh(s0n, l);
        float4 a1n = ld_xlh(s1n, l);

        float p0 = lrelu(a0.x + xr.x) * at4.x + lrelu(a0.y + xr.y) * at4.y
                 + lrelu(a0.z + xr.z) * at4.z + lrelu(a0.w + xr.w) * at4.w;
        float p1 = lrelu(a1.x + xr.x) * at4.x + lrelu(a1.y + xr.y) * at4.y
                 + lrelu(a1.z + xr.z) * at4.z + lrelu(a1.w + xr.w) * at4.w;
        p0 += __shfl_xor_sync(0xffffffffu, p0, 1, 8);
        p1 += __shfl_xor_sync(0xffffffffu, p1, 1, 8);
        p0 += __shfl_xor_sync(0xffffffffu, p0, 2, 8);
        p1 += __shfl_xor_sync(0xffffffffu, p1, 2, 8);
        p0 += __shfl_xor_sync(0xffffffffu, p0, 4, 8);
        p1 += __shfl_xor_sync(0xffffffffu, p1, 4, 8);
        float ex0 = v0 ? __expf(p0) : 0.f;       // scores O(1): no max shift
        float ex1 = v1 ? __expf(p1) : 0.f;
        acc.x = fmaf(ex0, a0.x, fmaf(ex1, a1.x, acc.x));
        acc.y = fmaf(ex0, a0.y, fmaf(ex1, a1.y, acc.y));
        acc.z = fmaf(ex0, a0.z, fmaf(ex1, a1.z, acc.z));
        acc.w = fmaf(ex0, a0.w, fmaf(ex1, a1.w, acc.w));
        dsum += ex0 + ex1;

        a0 = a0n; a1 = a1n; v0 = v0n; v1 = v1n;
    }

    acc.x += __shfl_xor_sync(0xffffffffu, acc.x, 16);
    acc.y += __shfl_xor_sync(0xffffffffu, acc.y, 16);
    acc.z += __shfl_xor_sync(0xffffffffu, acc.z, 16);
    acc.w += __shfl_xor_sync(0xffffffffu, acc.w, 16);
    dsum  += __shfl_xor_sync(0xffffffffu, dsum, 16);

    float inv = 1.f / (dsum + 1e-16f);
    float4 bo = *(const float4*)&bias_out[l * 4];
    float4 rx = *(const float4*)&g_x[w * 64 + l * 4];
    float y0 = acc.x * inv + bo.x;
    float y1 = acc.y * inv + bo.y;
    float y2 = acc.z * inv + bo.z;
    float y3 = acc.w * inv + bo.w;
    y0 = y0 > 0.f ? y0 : expm1f(y0);
    y1 = y1 > 0.f ? y1 : expm1f(y1);
    y2 = y2 > 0.f ? y2 : expm1f(y2);
    y3 = y3 > 0.f ? y3 : expm1f(y3);
    y0 += rx.x; y1 += rx.y; y2 += rx.z; y3 += rx.w;

    float sum = y0 + y1 + y2 + y3;
#pragma unroll
    for (int o = 1; o < 16; o <<= 1)
        sum += __shfl_xor_sync(0xffffffffu, sum, o, 16);
    float mu = sum * (1.f / 64.f);
    float d0 = y0 - mu, d1 = y1 - mu, d2 = y2 - mu, d3 = y3 - mu;
    float vs = d0 * d0 + d1 * d1 + d2 * d2 + d3 * d3;
#pragma unroll
    for (int o = 1; o < 16; o <<= 1)
        vs += __shfl_xor_sync(0xffffffffu, vs, o, 16);
    float r = rsqrtf(vs * (1.f / 64.f) + 1e-5f);

    float4 gm = *(const float4*)&gamma[l * 4];
    float4 bt = *(const float4*)&beta[l * 4];
    float4 o4;
    o4.x = nan2num(fmaf(d0 * r, gm.x, bt.x));
    o4.y = nan2num(fmaf(d1 * r, gm.y, bt.y));
    o4.z = nan2num(fmaf(d2 * r, gm.z, bt.z));
    o4.w = nan2num(fmaf(d3 * r, gm.w, bt.w));

    if (half == 0) {
        float* outp = to_dout ? dout : g_x;
        *(float4*)&outp[w * 64 + l * 4] = o4;
    }
}

// ---------------- host driver ----------------------------------------------
extern "C" void kernel_launch(void* const* d_in, const int* in_sizes, int n_in,
                              void* d_out, int out_size) {
    const float* coords   = (const float*)d_in[0];
    const int*   ei       = (const int*)  d_in[1];   // int32 (JAX x64 disabled)
    const float* Wp       = (const float*)d_in[2];
    const float* bp       = (const float*)d_in[3];
    const float* Wl       = (const float*)d_in[4];
    const float* bl       = (const float*)d_in[5];
    const float* Wr       = (const float*)d_in[6];
    const float* br       = (const float*)d_in[7];
    const float* att      = (const float*)d_in[8];
    const float* bias_out = (const float*)d_in[9];
    const float* gamma    = (const float*)d_in[10];
    const float* beta     = (const float*)d_in[11];
    float*       outp     = (float*)d_out;

    const int TB = 256;
    const int grid_nh = (NN * HID + TB - 1) / TB;    // 25000
    const int grid_gm = (NN + 127) / 128;            // 782
    const int grid_ep = (EP + TB - 1) / TB;          // 6641
    const int grid_ag = (NN * 32 + TB - 1) / TB;     // 12500 (warp/node)

    // projection + CSR build — once, reused by all layers.
    // gemm layer 0 at profiled position (4th launch).
    k_proj<<<grid_nh, TB>>>(coords, Wp, bp);
    k_hist<<<grid_ep, TB>>>(ei);
    k_scan1<<<NB1, SCAN_T>>>();
    k_gemm<<<grid_gm, TB>>>(Wl, bl, Wr, br);         // layer 0 (needs proj only)
    k_scan3<<<NB1, SCAN_T>>>();
    k_scatter<<<grid_ep, TB>>>(ei);

    for (int i = 0; i < LAYERS; i++) {
        if (i > 0)
            k_gemm<<<grid_gm, TB>>>(Wl + i * HID * HID, bl + i * HID,
                                    Wr + i * HID * HID, br + i * HID);
        k_aggr_ln<<<grid_ag, TB>>>(att + i * HID, bias_out + i * HID,
                                   gamma + i * HID, beta + i * HID,
                                   outp, (i == LAYERS - 1) ? 1 : 0);
    }
}